// round 1
// baseline (speedup 1.0000x reference)
#include <cuda_runtime.h>
#include <cstdint>

// Problem constants (from reference)
#define KK 16
#define YY 32
#define CC 16
#define NBUCKET (KK * YY)          // 512
#define ACC_ELEMS (NBUCKET * CC)   // 8192
#define EPS_F 1e-8f

// Scratch accumulator (no cudaMalloc allowed)
__device__ float g_acc[ACC_ELEMS];

// ---------------------------------------------------------------------------
// Kernel 0: zero the accumulator (must run every launch; graph replays reuse it)
// ---------------------------------------------------------------------------
__global__ void cc_zero_acc() {
    int i = blockIdx.x * blockDim.x + threadIdx.x;
    if (i < ACC_ELEMS) g_acc[i] = 0.0f;
}

// ---------------------------------------------------------------------------
// Kernel 1: scatter-add. One thread per float4 (quarter-row). Fully coalesced
// 16B loads; 4 consecutive lanes share a row's labels (L1 broadcast).
// red.global.add.v4.f32 (sm_90+) -> L2-side reduction, 1 op per 4 channels.
// ---------------------------------------------------------------------------
__global__ void cc_scatter(const int* __restrict__ xl,
                           const int* __restrict__ yl,
                           const float4* __restrict__ post,
                           int n_f4) {
    int stride = gridDim.x * blockDim.x;
    for (int i = blockIdx.x * blockDim.x + threadIdx.x; i < n_f4; i += stride) {
        int row = i >> 2;
        int c4  = i & 3;
        float4 v = post[i];
        int b = xl[row] * YY + yl[row];           // composite bucket in [0,512)
        float* dst = &g_acc[b * CC + c4 * 4];
        asm volatile("red.global.add.v4.f32 [%0], {%1, %2, %3, %4};"
                     :: "l"(dst), "f"(v.x), "f"(v.y), "f"(v.z), "f"(v.w)
                     : "memory");
    }
}

// ---------------------------------------------------------------------------
// Kernel 2: finalize. numerator = acc + eps; normalize over Y (axis=1).
// 256 threads = (k, c) pairs; each reduces 32 y-values (stride CC floats... 
// actually stride CC*1 within the k-block: acc[(k*YY+y)*CC + c]).
// ---------------------------------------------------------------------------
__global__ void cc_finalize(float* __restrict__ out) {
    int t = threadIdx.x;           // 0..255
    int k = t >> 4;
    int c = t & 15;
    float vals[YY];
    float s = 0.0f;
#pragma unroll
    for (int y = 0; y < YY; y++) {
        float v = g_acc[(k * YY + y) * CC + c] + EPS_F;
        vals[y] = v;
        s += v;
    }
    float inv = 1.0f / s;
#pragma unroll
    for (int y = 0; y < YY; y++) {
        out[(k * YY + y) * CC + c] = vals[y] * inv;
    }
}

// ---------------------------------------------------------------------------
// Launch
// ---------------------------------------------------------------------------
extern "C" void kernel_launch(void* const* d_in, const int* in_sizes, int n_in,
                              void* d_out, int out_size) {
    const int*    xl   = (const int*)d_in[0];           // x_labels [N] int32
    const int*    yl   = (const int*)d_in[1];           // y_labels [N] int32
    const float4* post = (const float4*)d_in[2];        // posterior [N,16] f32
    float* out = (float*)d_out;                         // [16,32,16] f32

    int n = in_sizes[0];                                // N rows
    int n_f4 = n * (CC / 4);                            // N*4 float4s

    cc_zero_acc<<<(ACC_ELEMS + 255) / 256, 256>>>();

    // Grid-stride: ~16 CTAs/SM * 148 SMs, 256 threads each
    int grid = 148 * 16;
    cc_scatter<<<grid, 256>>>(xl, yl, post, n_f4);

    cc_finalize<<<1, 256>>>(out);
}

// round 2
// speedup vs baseline: 1.4015x; 1.4015x over previous
#include <cuda_runtime.h>
#include <cstdint>

// Problem constants (from reference)
#define KK 16
#define YY 32
#define CC 16
#define NBUCKET (KK * YY)          // 512
#define ACC_ELEMS (NBUCKET * CC)   // 8192
#define NREP 16                    // accumulator replicas (spread L2 atomic traffic)
#define EPS_F 1e-8f

// Replicated scratch accumulator: 16 * 8192 floats = 512 KB
__device__ float g_acc[NREP * ACC_ELEMS];

// ---------------------------------------------------------------------------
// Kernel 0: zero all replicas.
// ---------------------------------------------------------------------------
__global__ void cc_zero_acc() {
    int i = blockIdx.x * blockDim.x + threadIdx.x;   // one float4 per thread
    float4* p = (float4*)g_acc;
    if (i < (NREP * ACC_ELEMS) / 4) p[i] = make_float4(0.f, 0.f, 0.f, 0.f);
}

// ---------------------------------------------------------------------------
// Kernel 1: scatter-add. One thread per float4 (quarter-row), fully coalesced
// 16B loads. red.global.add.v4.f32 into this CTA's replica.
// ---------------------------------------------------------------------------
__global__ void cc_scatter(const int* __restrict__ xl,
                           const int* __restrict__ yl,
                           const float4* __restrict__ post,
                           int n_f4) {
    int stride = gridDim.x * blockDim.x;
    int rep_base = (blockIdx.x & (NREP - 1)) * ACC_ELEMS;
    for (int i = blockIdx.x * blockDim.x + threadIdx.x; i < n_f4; i += stride) {
        int row = i >> 2;
        int c4  = i & 3;
        float4 v = post[i];
        int b = xl[row] * YY + yl[row];              // composite bucket [0,512)
        float* dst = &g_acc[rep_base + b * CC + c4 * 4];
        asm volatile("red.global.add.v4.f32 [%0], {%1, %2, %3, %4};"
                     :: "l"(dst), "f"(v.x), "f"(v.y), "f"(v.z), "f"(v.w)
                     : "memory");
    }
}

// ---------------------------------------------------------------------------
// Kernel 2: finalize. Reduce replicas -> smem, then add eps and normalize
// over Y (axis=1). One CTA of 512 threads.
// ---------------------------------------------------------------------------
__global__ void cc_finalize(float* __restrict__ out) {
    __shared__ float red[ACC_ELEMS];
    int tid = threadIdx.x;   // 0..511

    // Phase 1: replica reduction. Each thread handles 16 elements.
    for (int e = tid; e < ACC_ELEMS; e += 512) {
        float s = 0.0f;
#pragma unroll
        for (int r = 0; r < NREP; r++) s += g_acc[r * ACC_ELEMS + e];
        red[e] = s;
    }
    __syncthreads();

    // Phase 2: normalize over Y. 256 active threads = (k, c) pairs.
    if (tid < KK * CC) {
        int k = tid >> 4;
        int c = tid & 15;
        float vals[YY];
        float s = 0.0f;
#pragma unroll
        for (int y = 0; y < YY; y++) {
            float v = red[(k * YY + y) * CC + c] + EPS_F;
            vals[y] = v;
            s += v;
        }
        float inv = 1.0f / s;
#pragma unroll
        for (int y = 0; y < YY; y++) {
            out[(k * YY + y) * CC + c] = vals[y] * inv;
        }
    }
}

// ---------------------------------------------------------------------------
// Launch
// ---------------------------------------------------------------------------
extern "C" void kernel_launch(void* const* d_in, const int* in_sizes, int n_in,
                              void* d_out, int out_size) {
    const int*    xl   = (const int*)d_in[0];        // x_labels [N] int32
    const int*    yl   = (const int*)d_in[1];        // y_labels [N] int32
    const float4* post = (const float4*)d_in[2];     // posterior [N,16] f32
    float* out = (float*)d_out;                      // [16,32,16] f32

    int n = in_sizes[0];
    int n_f4 = n * (CC / 4);

    cc_zero_acc<<<(NREP * ACC_ELEMS / 4 + 255) / 256, 256>>>();

    int grid = 148 * 16;
    cc_scatter<<<grid, 256>>>(xl, yl, post, n_f4);

    cc_finalize<<<1, 512>>>(out);
}

// round 3
// speedup vs baseline: 1.4125x; 1.0078x over previous
#include <cuda_runtime.h>
#include <cstdint>

// Problem constants (from reference)
#define KK 16
#define YY 32
#define CC 16
#define NBUCKET (KK * YY)          // 512
#define ACC_ELEMS (NBUCKET * CC)   // 8192
#define NREP 16                    // accumulator replicas (spread L2 atomic traffic)
#define EPS_F 1e-8f

// Replicated scratch accumulator: 16 * 8192 floats = 512 KB
__device__ float g_acc[NREP * ACC_ELEMS];

// ---------------------------------------------------------------------------
// Kernel 0: zero all replicas.
// ---------------------------------------------------------------------------
__global__ void cc_zero_acc() {
    int i = blockIdx.x * blockDim.x + threadIdx.x;   // one float4 per thread
    float4* p = (float4*)g_acc;
    if (i < (NREP * ACC_ELEMS) / 4) p[i] = make_float4(0.f, 0.f, 0.f, 0.f);
}

// ---------------------------------------------------------------------------
// Kernel 1: scatter-add. One thread per float4 (quarter-row), fully coalesced
// 16B loads. red.global.add.v4.f32 into this CTA's replica.
// ---------------------------------------------------------------------------
__global__ void cc_scatter(const int* __restrict__ xl,
                           const int* __restrict__ yl,
                           const float4* __restrict__ post,
                           int n_f4) {
    int stride = gridDim.x * blockDim.x;
    int rep_base = (blockIdx.x & (NREP - 1)) * ACC_ELEMS;
    for (int i = blockIdx.x * blockDim.x + threadIdx.x; i < n_f4; i += stride) {
        int row = i >> 2;
        int c4  = i & 3;
        float4 v = post[i];
        int b = xl[row] * YY + yl[row];              // composite bucket [0,512)
        float* dst = &g_acc[rep_base + b * CC + c4 * 4];
        asm volatile("red.global.add.v4.f32 [%0], {%1, %2, %3, %4};"
                     :: "l"(dst), "f"(v.x), "f"(v.y), "f"(v.z), "f"(v.w)
                     : "memory");
    }
}

// ---------------------------------------------------------------------------
// Kernel 2: finalize. Reduce replicas -> smem, then add eps and normalize
// over Y (axis=1). One CTA of 512 threads.
// ---------------------------------------------------------------------------
__global__ void cc_finalize(float* __restrict__ out) {
    __shared__ float red[ACC_ELEMS];
    int tid = threadIdx.x;   // 0..511

    // Phase 1: replica reduction. Each thread handles 16 elements.
    for (int e = tid; e < ACC_ELEMS; e += 512) {
        float s = 0.0f;
#pragma unroll
        for (int r = 0; r < NREP; r++) s += g_acc[r * ACC_ELEMS + e];
        red[e] = s;
    }
    __syncthreads();

    // Phase 2: normalize over Y. 256 active threads = (k, c) pairs.
    if (tid < KK * CC) {
        int k = tid >> 4;
        int c = tid & 15;
        float vals[YY];
        float s = 0.0f;
#pragma unroll
        for (int y = 0; y < YY; y++) {
            float v = red[(k * YY + y) * CC + c] + EPS_F;
            vals[y] = v;
            s += v;
        }
        float inv = 1.0f / s;
#pragma unroll
        for (int y = 0; y < YY; y++) {
            out[(k * YY + y) * CC + c] = vals[y] * inv;
        }
    }
}

// ---------------------------------------------------------------------------
// Launch
// ---------------------------------------------------------------------------
extern "C" void kernel_launch(void* const* d_in, const int* in_sizes, int n_in,
                              void* d_out, int out_size) {
    const int*    xl   = (const int*)d_in[0];        // x_labels [N] int32
    const int*    yl   = (const int*)d_in[1];        // y_labels [N] int32
    const float4* post = (const float4*)d_in[2];     // posterior [N,16] f32
    float* out = (float*)d_out;                      // [16,32,16] f32

    int n = in_sizes[0];
    int n_f4 = n * (CC / 4);

    cc_zero_acc<<<(NREP * ACC_ELEMS / 4 + 255) / 256, 256>>>();

    int grid = 148 * 16;
    cc_scatter<<<grid, 256>>>(xl, yl, post, n_f4);

    cc_finalize<<<1, 512>>>(out);
}